// round 11
// baseline (speedup 1.0000x reference)
#include <cuda_runtime.h>

// ---------------- problem constants ----------------
constexpr int B_   = 128;
constexpr int T_   = 256;
constexpr int E_   = 384;
constexpr int H_   = 6;
constexpr int D_   = 64;
constexpr int DFF_ = 1536;
constexpr int L_   = 6;
constexpr int V_   = 65;
constexpr int M_   = B_ * T_;   // 32768 rows

// ---------------- scratch (device globals; no allocation allowed) ----------------
__device__ float g_x [M_ * E_];
__device__ float g_h [M_ * E_];
__device__ float g_q [M_ * E_];
__device__ float g_k [M_ * E_];
__device__ float g_v [M_ * E_];
__device__ float g_o [M_ * E_];
__device__ float g_ff[M_ * DFF_];

// ---------------- embedding + positional encoding ----------------
__global__ void embed_kernel(const int* __restrict__ tokens,
                             const float* __restrict__ pos,
                             const float* __restrict__ emb,
                             float* __restrict__ x)
{
    int idx = blockIdx.x * blockDim.x + threadIdx.x;
    if (idx >= M_ * E_) return;
    int bt = idx / E_;
    int e  = idx - bt * E_;
    int t  = bt % T_;
    int tok = tokens[bt];
    x[idx] = emb[tok * E_ + e] + pos[t * E_ + e];
}

// ---------------- layer norm: one warp per row ----------------
__global__ void ln_kernel(const float* __restrict__ x,
                          const float* __restrict__ g,
                          const float* __restrict__ b,
                          float* __restrict__ out)
{
    int row  = blockIdx.x * blockDim.y + threadIdx.y;
    int lane = threadIdx.x;
    const float* xr = x + (long)row * E_;

    float vals[E_ / 32];
    float s = 0.f;
    #pragma unroll
    for (int i = 0; i < E_ / 32; i++) {
        vals[i] = xr[lane + i * 32];
        s += vals[i];
    }
    #pragma unroll
    for (int off = 16; off > 0; off >>= 1) s += __shfl_xor_sync(0xFFFFFFFF, s, off);
    float mean = s * (1.0f / E_);

    float var = 0.f;
    #pragma unroll
    for (int i = 0; i < E_ / 32; i++) {
        float d = vals[i] - mean;
        var += d * d;
    }
    #pragma unroll
    for (int off = 16; off > 0; off >>= 1) var += __shfl_xor_sync(0xFFFFFFFF, var, off);
    float r = rsqrtf(var * (1.0f / E_) + 1e-5f);

    float* orow = out + (long)row * E_;
    #pragma unroll
    for (int i = 0; i < E_ / 32; i++) {
        int e = lane + i * 32;
        orow[e] = (vals[i] - mean) * r * g[e] + b[e];
    }
}

// ---------------- generic SGEMM: C = act(A@B + bias (+resid)) ----------------
// A: [M,K] row-major, B: [K,N] row-major. BM=BN=128, BK=8, 8x8 microtiles.
__global__ __launch_bounds__(256) void sgemm_kernel(
    const float* __restrict__ A, const float* __restrict__ Bm,
    const float* __restrict__ bias, const float* __restrict__ resid,
    float* __restrict__ C, int M, int N, int K, int do_relu)
{
    __shared__ float As[8][128];
    __shared__ float Bs[8][128];

    int bm = blockIdx.y * 128;
    int bn = blockIdx.x * 128;
    int tid = threadIdx.x;
    int trow = tid >> 4;          // 0..15
    int tcol = tid & 15;          // 0..15

    int a_m = tid >> 1;           // 0..127
    int a_k = (tid & 1) * 4;      // 0 or 4
    int b_k = tid >> 5;           // 0..7
    int b_n = (tid & 31) * 4;     // 0..124

    float acc[8][8];
    #pragma unroll
    for (int i = 0; i < 8; i++)
        #pragma unroll
        for (int j = 0; j < 8; j++) acc[i][j] = 0.f;

    for (int k0 = 0; k0 < K; k0 += 8) {
        int gm = bm + a_m;
        const float* aptr = A + (long)gm * K + k0 + a_k;
        #pragma unroll
        for (int i = 0; i < 4; i++)
            As[a_k + i][a_m] = aptr[i];            // K % 8 == 0 always here

        const float* bptr = Bm + (long)(k0 + b_k) * N + bn + b_n;
        #pragma unroll
        for (int i = 0; i < 4; i++) {
            int n = bn + b_n + i;
            Bs[b_k][b_n + i] = (n < N) ? bptr[i] : 0.f;
        }
        __syncthreads();

        #pragma unroll
        for (int kk = 0; kk < 8; kk++) {
            float a[8], b[8];
            #pragma unroll
            for (int i = 0; i < 8; i++) a[i] = As[kk][trow * 8 + i];
            #pragma unroll
            for (int j = 0; j < 8; j++) b[j] = Bs[kk][tcol * 8 + j];
            #pragma unroll
            for (int i = 0; i < 8; i++)
                #pragma unroll
                for (int j = 0; j < 8; j++)
                    acc[i][j] = fmaf(a[i], b[j], acc[i][j]);
        }
        __syncthreads();
    }

    #pragma unroll
    for (int i = 0; i < 8; i++) {
        int m = bm + trow * 8 + i;
        if (m >= M) continue;
        #pragma unroll
        for (int j = 0; j < 8; j++) {
            int n = bn + tcol * 8 + j;
            if (n >= N) continue;
            float v = acc[i][j] + bias[n];
            if (resid) v += resid[(long)m * N + n];
            if (do_relu) v = fmaxf(v, 0.f);
            C[(long)m * N + n] = v;
        }
    }
}

// ---------------- fused causal attention ----------------
// One block per (b, h). 256 threads; thread t owns query row t.
// K/V staged in shared (128 KB); Q + accumulator in registers; online softmax.
constexpr int ATTN_SMEM = 2 * T_ * D_ * (int)sizeof(float);   // 131072

__global__ __launch_bounds__(256) void attn_kernel(
    const float* __restrict__ q, const float* __restrict__ k,
    const float* __restrict__ v, float* __restrict__ o)
{
    extern __shared__ float sm[];
    float* Ks = sm;
    float* Vs = sm + T_ * D_;

    int bh = blockIdx.x;
    int b  = bh / H_;
    int h  = bh - b * H_;
    int tid = threadIdx.x;

    // stage K,V for this (b,h)
    for (int i = tid; i < T_ * D_; i += 256) {
        int t = i >> 6;          // /64
        int d = i & 63;
        long gidx = ((long)(b * T_ + t)) * E_ + h * D_ + d;
        Ks[i] = k[gidx];
        Vs[i] = v[gidx];
    }
    __syncthreads();

    // load own Q row into registers
    float qreg[D_];
    {
        const float4* qp = (const float4*)(q + ((long)(b * T_ + tid)) * E_ + h * D_);
        #pragma unroll
        for (int i = 0; i < D_ / 4; i++) {
            float4 f = qp[i];
            qreg[4 * i + 0] = f.x; qreg[4 * i + 1] = f.y;
            qreg[4 * i + 2] = f.z; qreg[4 * i + 3] = f.w;
        }
    }

    const float scale = 0.125f;   // 1/sqrt(64)
    float mrun = -1e30f;
    float lrun = 0.f;
    float acc[D_];
    #pragma unroll
    for (int d = 0; d < D_; d++) acc[d] = 0.f;

    for (int kk = 0; kk <= tid; kk++) {
        const float4* kp = (const float4*)(Ks + kk * D_);
        float s = 0.f;
        #pragma unroll
        for (int i = 0; i < D_ / 4; i++) {
            float4 f = kp[i];
            s = fmaf(qreg[4 * i + 0], f.x, s);
            s = fmaf(qreg[4 * i + 1], f.y, s);
            s = fmaf(qreg[4 * i + 2], f.z, s);
            s = fmaf(qreg[4 * i + 3], f.w, s);
        }
        s *= scale;
        if (s > mrun) {
            float corr = __expf(mrun - s);
            lrun *= corr;
            #pragma unroll
            for (int d = 0; d < D_; d++) acc[d] *= corr;
            mrun = s;
        }
        float p = __expf(s - mrun);
        lrun += p;
        const float4* vp = (const float4*)(Vs + kk * D_);
        #pragma unroll
        for (int i = 0; i < D_ / 4; i++) {
            float4 f = vp[i];
            acc[4 * i + 0] = fmaf(p, f.x, acc[4 * i + 0]);
            acc[4 * i + 1] = fmaf(p, f.y, acc[4 * i + 1]);
            acc[4 * i + 2] = fmaf(p, f.z, acc[4 * i + 2]);
            acc[4 * i + 3] = fmaf(p, f.w, acc[4 * i + 3]);
        }
    }

    float inv = 1.f / lrun;
    float* orow = o + ((long)(b * T_ + tid)) * E_ + h * D_;
    #pragma unroll
    for (int d = 0; d < D_; d++) orow[d] = acc[d] * inv;
}

// ---------------- orchestration ----------------
extern "C" void kernel_launch(void* const* d_in, const int* in_sizes, int n_in,
                              void* d_out, int out_size)
{
    const int*   tokens = (const int*)  d_in[0];
    const float* pos    = (const float*)d_in[1];
    const float* emb    = (const float*)d_in[2];
    const float* Wq     = (const float*)d_in[3];
    const float* bq     = (const float*)d_in[4];
    const float* Wk     = (const float*)d_in[5];
    const float* bk     = (const float*)d_in[6];
    const float* Wv     = (const float*)d_in[7];
    const float* bv     = (const float*)d_in[8];
    const float* Wo     = (const float*)d_in[9];
    const float* bo     = (const float*)d_in[10];
    const float* ln1_g  = (const float*)d_in[11];
    const float* ln1_b  = (const float*)d_in[12];
    const float* W1     = (const float*)d_in[13];
    const float* c1     = (const float*)d_in[14];
    const float* W2     = (const float*)d_in[15];
    const float* c2     = (const float*)d_in[16];
    const float* ln2_g  = (const float*)d_in[17];
    const float* ln2_b  = (const float*)d_in[18];
    const float* Wl     = (const float*)d_in[19];
    const float* bl     = (const float*)d_in[20];
    float* out = (float*)d_out;

    float *x, *h, *q, *k, *v, *o, *ff;
    cudaGetSymbolAddress((void**)&x,  g_x);
    cudaGetSymbolAddress((void**)&h,  g_h);
    cudaGetSymbolAddress((void**)&q,  g_q);
    cudaGetSymbolAddress((void**)&k,  g_k);
    cudaGetSymbolAddress((void**)&v,  g_v);
    cudaGetSymbolAddress((void**)&o,  g_o);
    cudaGetSymbolAddress((void**)&ff, g_ff);

    cudaFuncSetAttribute(attn_kernel,
                         cudaFuncAttributeMaxDynamicSharedMemorySize, ATTN_SMEM);

    embed_kernel<<<(M_ * E_ + 255) / 256, 256>>>(tokens, pos, emb, x);

    dim3 lnGrid(M_ / 4);
    dim3 lnBlk(32, 4);
    dim3 gE(E_ / 128, M_ / 128);      // N=384
    dim3 gF(DFF_ / 128, M_ / 128);    // N=1536
    dim3 gL(1, M_ / 128);             // N=65

    for (int l = 0; l < L_; l++) {
        size_t wEE = (size_t)l * E_ * E_;
        size_t wEF = (size_t)l * E_ * DFF_;

        ln_kernel<<<lnGrid, lnBlk>>>(x, ln1_g + l * E_, ln1_b + l * E_, h);

        sgemm_kernel<<<gE, 256>>>(h, Wq + wEE, bq + l * E_, nullptr, q, M_, E_, E_, 0);
        sgemm_kernel<<<gE, 256>>>(h, Wk + wEE, bk + l * E_, nullptr, k, M_, E_, E_, 0);
        sgemm_kernel<<<gE, 256>>>(h, Wv + wEE, bv + l * E_, nullptr, v, M_, E_, E_, 0);

        attn_kernel<<<B_ * H_, 256, ATTN_SMEM>>>(q, k, v, o);

        sgemm_kernel<<<gE, 256>>>(o, Wo + wEE, bo + l * E_, x, x, M_, E_, E_, 0);

        ln_kernel<<<lnGrid, lnBlk>>>(x, ln2_g + l * E_, ln2_b + l * E_, h);

        sgemm_kernel<<<gF, 256>>>(h, W1 + wEF, c1 + l * DFF_, nullptr, ff, M_, DFF_, E_, 1);
        sgemm_kernel<<<gE, 256>>>(ff, W2 + wEF, c2 + l * E_, x, x, M_, E_, DFF_, 0);
    }

    sgemm_kernel<<<gL, 256>>>(x, Wl, bl, nullptr, out, M_, V_, E_, 0);
}

// round 12
// speedup vs baseline: 1.6010x; 1.6010x over previous
#include <cuda_runtime.h>

// ---------------- problem constants ----------------
constexpr int B_   = 128;
constexpr int T_   = 256;
constexpr int E_   = 384;
constexpr int H_   = 6;
constexpr int D_   = 64;
constexpr int DFF_ = 1536;
constexpr int L_   = 6;
constexpr int V_   = 65;
constexpr int M_   = B_ * T_;   // 32768 rows

// ---------------- scratch (device globals; no allocation allowed) ----------------
__device__ float g_x [M_ * E_];
__device__ float g_h [M_ * E_];
__device__ float g_q [M_ * E_];
__device__ float g_k [M_ * E_];
__device__ float g_v [M_ * E_];
__device__ float g_o [M_ * E_];
__device__ float g_ff[M_ * DFF_];

// ---------------- embedding + positional encoding ----------------
__global__ void embed_kernel(const int* __restrict__ tokens,
                             const float* __restrict__ pos,
                             const float* __restrict__ emb,
                             float* __restrict__ x)
{
    int idx = blockIdx.x * blockDim.x + threadIdx.x;
    if (idx >= M_ * E_) return;
    int bt = idx / E_;
    int e  = idx - bt * E_;
    int t  = bt % T_;
    int tok = tokens[bt];
    x[idx] = emb[tok * E_ + e] + pos[t * E_ + e];
}

// ---------------- layer norm: one warp per row ----------------
__global__ void ln_kernel(const float* __restrict__ x,
                          const float* __restrict__ g,
                          const float* __restrict__ b,
                          float* __restrict__ out)
{
    int row  = blockIdx.x * blockDim.y + threadIdx.y;
    int lane = threadIdx.x;
    const float* xr = x + (long)row * E_;

    float vals[E_ / 32];
    float s = 0.f;
    #pragma unroll
    for (int i = 0; i < E_ / 32; i++) {
        vals[i] = xr[lane + i * 32];
        s += vals[i];
    }
    #pragma unroll
    for (int off = 16; off > 0; off >>= 1) s += __shfl_xor_sync(0xFFFFFFFF, s, off);
    float mean = s * (1.0f / E_);

    float var = 0.f;
    #pragma unroll
    for (int i = 0; i < E_ / 32; i++) {
        float d = vals[i] - mean;
        var += d * d;
    }
    #pragma unroll
    for (int off = 16; off > 0; off >>= 1) var += __shfl_xor_sync(0xFFFFFFFF, var, off);
    float r = rsqrtf(var * (1.0f / E_) + 1e-5f);

    float* orow = out + (long)row * E_;
    #pragma unroll
    for (int i = 0; i < E_ / 32; i++) {
        int e = lane + i * 32;
        orow[e] = (vals[i] - mean) * r * g[e] + b[e];
    }
}

// ---------------- generic SGEMM: C = act(A@B + bias (+resid)) ----------------
// A: [M,K] row-major, B: [K,N] row-major. BM=BN=128, BK=8, 8x8 microtiles.
__global__ __launch_bounds__(256) void sgemm_kernel(
    const float* __restrict__ A, const float* __restrict__ Bm,
    const float* __restrict__ bias, const float* __restrict__ resid,
    float* __restrict__ C, int M, int N, int K, int do_relu)
{
    __shared__ float As[8][128];
    __shared__ float Bs[8][128];

    int bm = blockIdx.y * 128;
    int bn = blockIdx.x * 128;
    int tid = threadIdx.x;
    int trow = tid >> 4;          // 0..15
    int tcol = tid & 15;          // 0..15

    int a_m = tid >> 1;           // 0..127
    int a_k = (tid & 1) * 4;      // 0 or 4
    int b_k = tid >> 5;           // 0..7
    int b_n = (tid & 31) * 4;     // 0..124

    float acc[8][8];
    #pragma unroll
    for (int i = 0; i < 8; i++)
        #pragma unroll
        for (int j = 0; j < 8; j++) acc[i][j] = 0.f;

    for (int k0 = 0; k0 < K; k0 += 8) {
        int gm = bm + a_m;
        const float* aptr = A + (long)gm * K + k0 + a_k;
        #pragma unroll
        for (int i = 0; i < 4; i++)
            As[a_k + i][a_m] = aptr[i];            // K % 8 == 0 always here

        const float* bptr = Bm + (long)(k0 + b_k) * N + bn + b_n;
        #pragma unroll
        for (int i = 0; i < 4; i++) {
            int n = bn + b_n + i;
            Bs[b_k][b_n + i] = (n < N) ? bptr[i] : 0.f;
        }
        __syncthreads();

        #pragma unroll
        for (int kk = 0; kk < 8; kk++) {
            float a[8], b[8];
            #pragma unroll
            for (int i = 0; i < 8; i++) a[i] = As[kk][trow * 8 + i];
            #pragma unroll
            for (int j = 0; j < 8; j++) b[j] = Bs[kk][tcol * 8 + j];
            #pragma unroll
            for (int i = 0; i < 8; i++)
                #pragma unroll
                for (int j = 0; j < 8; j++)
                    acc[i][j] = fmaf(a[i], b[j], acc[i][j]);
        }
        __syncthreads();
    }

    #pragma unroll
    for (int i = 0; i < 8; i++) {
        int m = bm + trow * 8 + i;
        if (m >= M) continue;
        #pragma unroll
        for (int j = 0; j < 8; j++) {
            int n = bn + tcol * 8 + j;
            if (n >= N) continue;
            float v = acc[i][j] + bias[n];
            if (resid) v += resid[(long)m * N + n];
            if (do_relu) v = fmaxf(v, 0.f);
            C[(long)m * N + n] = v;
        }
    }
}

// ---------------- fused causal attention ----------------
// One block per (b, h). 256 threads; thread t owns query row t.
// K/V staged in shared (128 KB); Q + accumulator in registers; online softmax.
constexpr int ATTN_SMEM = 2 * T_ * D_ * (int)sizeof(float);   // 131072

__global__ __launch_bounds__(256) void attn_kernel(
    const float* __restrict__ q, const float* __restrict__ k,
    const float* __restrict__ v, float* __restrict__ o)
{
    extern __shared__ float sm[];
    float* Ks = sm;
    float* Vs = sm + T_ * D_;

    int bh = blockIdx.x;
    int b  = bh / H_;
    int h  = bh - b * H_;
    int tid = threadIdx.x;

    // stage K,V for this (b,h)
    for (int i = tid; i < T_ * D_; i += 256) {
        int t = i >> 6;          // /64
        int d = i & 63;
        long gidx = ((long)(b * T_ + t)) * E_ + h * D_ + d;
        Ks[i] = k[gidx];
        Vs[i] = v[gidx];
    }
    __syncthreads();

    // load own Q row into registers
    float qreg[D_];
    {
        const float4* qp = (const float4*)(q + ((long)(b * T_ + tid)) * E_ + h * D_);
        #pragma unroll
        for (int i = 0; i < D_ / 4; i++) {
            float4 f = qp[i];
            qreg[4 * i + 0] = f.x; qreg[4 * i + 1] = f.y;
            qreg[4 * i + 2] = f.z; qreg[4 * i + 3] = f.w;
        }
    }

    const float scale = 0.125f;   // 1/sqrt(64)
    float mrun = -1e30f;
    float lrun = 0.f;
    float acc[D_];
    #pragma unroll
    for (int d = 0; d < D_; d++) acc[d] = 0.f;

    for (int kk = 0; kk <= tid; kk++) {
        const float4* kp = (const float4*)(Ks + kk * D_);
        float s = 0.f;
        #pragma unroll
        for (int i = 0; i < D_ / 4; i++) {
            float4 f = kp[i];
            s = fmaf(qreg[4 * i + 0], f.x, s);
            s = fmaf(qreg[4 * i + 1], f.y, s);
            s = fmaf(qreg[4 * i + 2], f.z, s);
            s = fmaf(qreg[4 * i + 3], f.w, s);
        }
        s *= scale;
        if (s > mrun) {
            float corr = __expf(mrun - s);
            lrun *= corr;
            #pragma unroll
            for (int d = 0; d < D_; d++) acc[d] *= corr;
            mrun = s;
        }
        float p = __expf(s - mrun);
        lrun += p;
        const float4* vp = (const float4*)(Vs + kk * D_);
        #pragma unroll
        for (int i = 0; i < D_ / 4; i++) {
            float4 f = vp[i];
            acc[4 * i + 0] = fmaf(p, f.x, acc[4 * i + 0]);
            acc[4 * i + 1] = fmaf(p, f.y, acc[4 * i + 1]);
            acc[4 * i + 2] = fmaf(p, f.z, acc[4 * i + 2]);
            acc[4 * i + 3] = fmaf(p, f.w, acc[4 * i + 3]);
        }
    }

    float inv = 1.f / lrun;
    float* orow = o + ((long)(b * T_ + tid)) * E_ + h * D_;
    #pragma unroll
    for (int d = 0; d < D_; d++) orow[d] = acc[d] * inv;
}

// ---------------- orchestration ----------------
extern "C" void kernel_launch(void* const* d_in, const int* in_sizes, int n_in,
                              void* d_out, int out_size)
{
    const int*   tokens = (const int*)  d_in[0];
    const float* pos    = (const float*)d_in[1];
    const float* emb    = (const float*)d_in[2];
    const float* Wq     = (const float*)d_in[3];
    const float* bq     = (const float*)d_in[4];
    const float* Wk     = (const float*)d_in[5];
    const float* bk     = (const float*)d_in[6];
    const float* Wv     = (const float*)d_in[7];
    const float* bv     = (const float*)d_in[8];
    const float* Wo     = (const float*)d_in[9];
    const float* bo     = (const float*)d_in[10];
    const float* ln1_g  = (const float*)d_in[11];
    const float* ln1_b  = (const float*)d_in[12];
    const float* W1     = (const float*)d_in[13];
    const float* c1     = (const float*)d_in[14];
    const float* W2     = (const float*)d_in[15];
    const float* c2     = (const float*)d_in[16];
    const float* ln2_g  = (const float*)d_in[17];
    const float* ln2_b  = (const float*)d_in[18];
    const float* Wl     = (const float*)d_in[19];
    const float* bl     = (const float*)d_in[20];
    float* out = (float*)d_out;

    float *x, *h, *q, *k, *v, *o, *ff;
    cudaGetSymbolAddress((void**)&x,  g_x);
    cudaGetSymbolAddress((void**)&h,  g_h);
    cudaGetSymbolAddress((void**)&q,  g_q);
    cudaGetSymbolAddress((void**)&k,  g_k);
    cudaGetSymbolAddress((void**)&v,  g_v);
    cudaGetSymbolAddress((void**)&o,  g_o);
    cudaGetSymbolAddress((void**)&ff, g_ff);

    cudaFuncSetAttribute(attn_kernel,
                         cudaFuncAttributeMaxDynamicSharedMemorySize, ATTN_SMEM);

    embed_kernel<<<(M_ * E_ + 255) / 256, 256>>>(tokens, pos, emb, x);

    dim3 lnGrid(M_ / 4);
    dim3 lnBlk(32, 4);
    dim3 gE(E_ / 128, M_ / 128);      // N=384
    dim3 gF(DFF_ / 128, M_ / 128);    // N=1536
    dim3 gL(1, M_ / 128);             // N=65

    for (int l = 0; l < L_; l++) {
        size_t wEE = (size_t)l * E_ * E_;
        size_t wEF = (size_t)l * E_ * DFF_;

        ln_kernel<<<lnGrid, lnBlk>>>(x, ln1_g + l * E_, ln1_b + l * E_, h);

        sgemm_kernel<<<gE, 256>>>(h, Wq + wEE, bq + l * E_, nullptr, q, M_, E_, E_, 0);
        sgemm_kernel<<<gE, 256>>>(h, Wk + wEE, bk + l * E_, nullptr, k, M_, E_, E_, 0);
        sgemm_kernel<<<gE, 256>>>(h, Wv + wEE, bv + l * E_, nullptr, v, M_, E_, E_, 0);

        attn_kernel<<<B_ * H_, 256, ATTN_SMEM>>>(q, k, v, o);

        sgemm_kernel<<<gE, 256>>>(o, Wo + wEE, bo + l * E_, x, x, M_, E_, E_, 0);

        ln_kernel<<<lnGrid, lnBlk>>>(x, ln2_g + l * E_, ln2_b + l * E_, h);

        sgemm_kernel<<<gF, 256>>>(h, W1 + wEF, c1 + l * DFF_, nullptr, ff, M_, DFF_, E_, 1);
        sgemm_kernel<<<gE, 256>>>(ff, W2 + wEF, c2 + l * E_, x, x, M_, E_, DFF_, 0);
    }

    sgemm_kernel<<<gL, 256>>>(x, Wl, bl, nullptr, out, M_, V_, E_, 0);
}

// round 13
// speedup vs baseline: 1.6073x; 1.0039x over previous
#include <cuda_runtime.h>

// ---------------- problem constants ----------------
constexpr int B_   = 128;
constexpr int T_   = 256;
constexpr int E_   = 384;
constexpr int H_   = 6;
constexpr int D_   = 64;
constexpr int DFF_ = 1536;
constexpr int L_   = 6;
constexpr int V_   = 65;
constexpr int M_   = B_ * T_;   // 32768 rows

// ---------------- scratch (device globals; no allocation allowed) ----------------
__device__ float g_x [M_ * E_];
__device__ float g_h [M_ * E_];
__device__ float g_q [M_ * E_];
__device__ float g_k [M_ * E_];
__device__ float g_v [M_ * E_];
__device__ float g_o [M_ * E_];
__device__ float g_ff[M_ * DFF_];

// ---------------- embedding + positional encoding ----------------
__global__ void embed_kernel(const int* __restrict__ tokens,
                             const float* __restrict__ pos,
                             const float* __restrict__ emb,
                             float* __restrict__ x)
{
    int idx = blockIdx.x * blockDim.x + threadIdx.x;
    if (idx >= M_ * E_) return;
    int bt = idx / E_;
    int e  = idx - bt * E_;
    int t  = bt % T_;
    int tok = tokens[bt];
    x[idx] = emb[tok * E_ + e] + pos[t * E_ + e];
}

// ---------------- layer norm: one warp per row ----------------
__global__ void ln_kernel(const float* __restrict__ x,
                          const float* __restrict__ g,
                          const float* __restrict__ b,
                          float* __restrict__ out)
{
    int row  = blockIdx.x * blockDim.y + threadIdx.y;
    int lane = threadIdx.x;
    const float* xr = x + (long)row * E_;

    float vals[E_ / 32];
    float s = 0.f;
    #pragma unroll
    for (int i = 0; i < E_ / 32; i++) {
        vals[i] = xr[lane + i * 32];
        s += vals[i];
    }
    #pragma unroll
    for (int off = 16; off > 0; off >>= 1) s += __shfl_xor_sync(0xFFFFFFFF, s, off);
    float mean = s * (1.0f / E_);

    float var = 0.f;
    #pragma unroll
    for (int i = 0; i < E_ / 32; i++) {
        float d = vals[i] - mean;
        var += d * d;
    }
    #pragma unroll
    for (int off = 16; off > 0; off >>= 1) var += __shfl_xor_sync(0xFFFFFFFF, var, off);
    float r = rsqrtf(var * (1.0f / E_) + 1e-5f);

    float* orow = out + (long)row * E_;
    #pragma unroll
    for (int i = 0; i < E_ / 32; i++) {
        int e = lane + i * 32;
        orow[e] = (vals[i] - mean) * r * g[e] + b[e];
    }
}

// ---------------- generic SGEMM: C = act(A@B + bias (+resid)) ----------------
// A: [M,K] row-major, B: [K,N] row-major. BM=BN=128, BK=8, 8x8 microtiles.
__global__ __launch_bounds__(256) void sgemm_kernel(
    const float* __restrict__ A, const float* __restrict__ Bm,
    const float* __restrict__ bias, const float* __restrict__ resid,
    float* __restrict__ C, int M, int N, int K, int do_relu)
{
    __shared__ float As[8][128];
    __shared__ float Bs[8][128];

    int bm = blockIdx.y * 128;
    int bn = blockIdx.x * 128;
    int tid = threadIdx.x;
    int trow = tid >> 4;          // 0..15
    int tcol = tid & 15;          // 0..15

    int a_m = tid >> 1;           // 0..127
    int a_k = (tid & 1) * 4;      // 0 or 4
    int b_k = tid >> 5;           // 0..7
    int b_n = (tid & 31) * 4;     // 0..124

    float acc[8][8];
    #pragma unroll
    for (int i = 0; i < 8; i++)
        #pragma unroll
        for (int j = 0; j < 8; j++) acc[i][j] = 0.f;

    for (int k0 = 0; k0 < K; k0 += 8) {
        int gm = bm + a_m;
        const float* aptr = A + (long)gm * K + k0 + a_k;
        #pragma unroll
        for (int i = 0; i < 4; i++)
            As[a_k + i][a_m] = aptr[i];            // K % 8 == 0 always here

        const float* bptr = Bm + (long)(k0 + b_k) * N + bn + b_n;
        #pragma unroll
        for (int i = 0; i < 4; i++) {
            int n = bn + b_n + i;
            Bs[b_k][b_n + i] = (n < N) ? bptr[i] : 0.f;
        }
        __syncthreads();

        #pragma unroll
        for (int kk = 0; kk < 8; kk++) {
            float a[8], b[8];
            #pragma unroll
            for (int i = 0; i < 8; i++) a[i] = As[kk][trow * 8 + i];
            #pragma unroll
            for (int j = 0; j < 8; j++) b[j] = Bs[kk][tcol * 8 + j];
            #pragma unroll
            for (int i = 0; i < 8; i++)
                #pragma unroll
                for (int j = 0; j < 8; j++)
                    acc[i][j] = fmaf(a[i], b[j], acc[i][j]);
        }
        __syncthreads();
    }

    #pragma unroll
    for (int i = 0; i < 8; i++) {
        int m = bm + trow * 8 + i;
        if (m >= M) continue;
        #pragma unroll
        for (int j = 0; j < 8; j++) {
            int n = bn + tcol * 8 + j;
            if (n >= N) continue;
            float v = acc[i][j] + bias[n];
            if (resid) v += resid[(long)m * N + n];
            if (do_relu) v = fmaxf(v, 0.f);
            C[(long)m * N + n] = v;
        }
    }
}

// ---------------- fused causal attention ----------------
// One block per (b, h). 256 threads; thread t owns query row t.
// K/V staged in shared (128 KB); Q + accumulator in registers; online softmax.
constexpr int ATTN_SMEM = 2 * T_ * D_ * (int)sizeof(float);   // 131072

__global__ __launch_bounds__(256) void attn_kernel(
    const float* __restrict__ q, const float* __restrict__ k,
    const float* __restrict__ v, float* __restrict__ o)
{
    extern __shared__ float sm[];
    float* Ks = sm;
    float* Vs = sm + T_ * D_;

    int bh = blockIdx.x;
    int b  = bh / H_;
    int h  = bh - b * H_;
    int tid = threadIdx.x;

    // stage K,V for this (b,h)
    for (int i = tid; i < T_ * D_; i += 256) {
        int t = i >> 6;          // /64
        int d = i & 63;
        long gidx = ((long)(b * T_ + t)) * E_ + h * D_ + d;
        Ks[i] = k[gidx];
        Vs[i] = v[gidx];
    }
    __syncthreads();

    // load own Q row into registers
    float qreg[D_];
    {
        const float4* qp = (const float4*)(q + ((long)(b * T_ + tid)) * E_ + h * D_);
        #pragma unroll
        for (int i = 0; i < D_ / 4; i++) {
            float4 f = qp[i];
            qreg[4 * i + 0] = f.x; qreg[4 * i + 1] = f.y;
            qreg[4 * i + 2] = f.z; qreg[4 * i + 3] = f.w;
        }
    }

    const float scale = 0.125f;   // 1/sqrt(64)
    float mrun = -1e30f;
    float lrun = 0.f;
    float acc[D_];
    #pragma unroll
    for (int d = 0; d < D_; d++) acc[d] = 0.f;

    for (int kk = 0; kk <= tid; kk++) {
        const float4* kp = (const float4*)(Ks + kk * D_);
        float s = 0.f;
        #pragma unroll
        for (int i = 0; i < D_ / 4; i++) {
            float4 f = kp[i];
            s = fmaf(qreg[4 * i + 0], f.x, s);
            s = fmaf(qreg[4 * i + 1], f.y, s);
            s = fmaf(qreg[4 * i + 2], f.z, s);
            s = fmaf(qreg[4 * i + 3], f.w, s);
        }
        s *= scale;
        if (s > mrun) {
            float corr = __expf(mrun - s);
            lrun *= corr;
            #pragma unroll
            for (int d = 0; d < D_; d++) acc[d] *= corr;
            mrun = s;
        }
        float p = __expf(s - mrun);
        lrun += p;
        const float4* vp = (const float4*)(Vs + kk * D_);
        #pragma unroll
        for (int i = 0; i < D_ / 4; i++) {
            float4 f = vp[i];
            acc[4 * i + 0] = fmaf(p, f.x, acc[4 * i + 0]);
            acc[4 * i + 1] = fmaf(p, f.y, acc[4 * i + 1]);
            acc[4 * i + 2] = fmaf(p, f.z, acc[4 * i + 2]);
            acc[4 * i + 3] = fmaf(p, f.w, acc[4 * i + 3]);
        }
    }

    float inv = 1.f / lrun;
    float* orow = o + ((long)(b * T_ + tid)) * E_ + h * D_;
    #pragma unroll
    for (int d = 0; d < D_; d++) orow[d] = acc[d] * inv;
}

// ---------------- orchestration ----------------
extern "C" void kernel_launch(void* const* d_in, const int* in_sizes, int n_in,
                              void* d_out, int out_size)
{
    const int*   tokens = (const int*)  d_in[0];
    const float* pos    = (const float*)d_in[1];
    const float* emb    = (const float*)d_in[2];
    const float* Wq     = (const float*)d_in[3];
    const float* bq     = (const float*)d_in[4];
    const float* Wk     = (const float*)d_in[5];
    const float* bk     = (const float*)d_in[6];
    const float* Wv     = (const float*)d_in[7];
    const float* bv     = (const float*)d_in[8];
    const float* Wo     = (const float*)d_in[9];
    const float* bo     = (const float*)d_in[10];
    const float* ln1_g  = (const float*)d_in[11];
    const float* ln1_b  = (const float*)d_in[12];
    const float* W1     = (const float*)d_in[13];
    const float* c1     = (const float*)d_in[14];
    const float* W2     = (const float*)d_in[15];
    const float* c2     = (const float*)d_in[16];
    const float* ln2_g  = (const float*)d_in[17];
    const float* ln2_b  = (const float*)d_in[18];
    const float* Wl     = (const float*)d_in[19];
    const float* bl     = (const float*)d_in[20];
    float* out = (float*)d_out;

    float *x, *h, *q, *k, *v, *o, *ff;
    cudaGetSymbolAddress((void**)&x,  g_x);
    cudaGetSymbolAddress((void**)&h,  g_h);
    cudaGetSymbolAddress((void**)&q,  g_q);
    cudaGetSymbolAddress((void**)&k,  g_k);
    cudaGetSymbolAddress((void**)&v,  g_v);
    cudaGetSymbolAddress((void**)&o,  g_o);
    cudaGetSymbolAddress((void**)&ff, g_ff);

    cudaFuncSetAttribute(attn_kernel,
                         cudaFuncAttributeMaxDynamicSharedMemorySize, ATTN_SMEM);

    embed_kernel<<<(M_ * E_ + 255) / 256, 256>>>(tokens, pos, emb, x);

    dim3 lnGrid(M_ / 4);
    dim3 lnBlk(32, 4);
    dim3 gE(E_ / 128, M_ / 128);      // N=384
    dim3 gF(DFF_ / 128, M_ / 128);    // N=1536
    dim3 gL(1, M_ / 128);             // N=65

    for (int l = 0; l < L_; l++) {
        size_t wEE = (size_t)l * E_ * E_;
        size_t wEF = (size_t)l * E_ * DFF_;

        ln_kernel<<<lnGrid, lnBlk>>>(x, ln1_g + l * E_, ln1_b + l * E_, h);

        sgemm_kernel<<<gE, 256>>>(h, Wq + wEE, bq + l * E_, nullptr, q, M_, E_, E_, 0);
        sgemm_kernel<<<gE, 256>>>(h, Wk + wEE, bk + l * E_, nullptr, k, M_, E_, E_, 0);
        sgemm_kernel<<<gE, 256>>>(h, Wv + wEE, bv + l * E_, nullptr, v, M_, E_, E_, 0);

        attn_kernel<<<B_ * H_, 256, ATTN_SMEM>>>(q, k, v, o);

        sgemm_kernel<<<gE, 256>>>(o, Wo + wEE, bo + l * E_, x, x, M_, E_, E_, 0);

        ln_kernel<<<lnGrid, lnBlk>>>(x, ln2_g + l * E_, ln2_b + l * E_, h);

        sgemm_kernel<<<gF, 256>>>(h, W1 + wEF, c1 + l * DFF_, nullptr, ff, M_, DFF_, E_, 1);
        sgemm_kernel<<<gE, 256>>>(ff, W2 + wEF, c2 + l * E_, x, x, M_, E_, DFF_, 0);
    }

    sgemm_kernel<<<gL, 256>>>(x, Wl, bl, nullptr, out, M_, V_, E_, 0);
}